// round 8
// baseline (speedup 1.0000x reference)
#include <cuda_runtime.h>
#include <cuda_fp16.h>
#include <math.h>
#include <stdint.h>

#define Vv  32000
#define Ee  512
#define Hh  512
#define Bb  16
#define Ss  128
#define G4  2048   // 4*H
#define MBr 2048   // S*B rows

// ---------------- scratch (static device memory; no allocation) ----------------
__device__ __half g_x0h[(size_t)MBr * Ee];        // layer0 input (fp16)
__device__ __half g_x1h[(size_t)MBr * 1024];      // layer1 input (fp16)
__device__ float  g_xg[2][(size_t)MBr * G4];      // per-dir gate preacts (fp32)
__device__ float  g_h[2][2][Bb * Hh];             // [parity][dir][b*H] (fp32)
__device__ __half g_hfinh[(size_t)Bb * Ss * 1024];// layer1 output (fp16)
__device__ __half g_wth[(size_t)Vv * 1024];       // lin_w fp16
__device__ __half g_wph[(size_t)4096 * 1024];     // packed Wih fp16 (both dirs)
__device__ float  g_bias[4096];                   // combined bih+bhh (both dirs)
__device__ unsigned g_bar_cnt[2];
__device__ unsigned g_bar_gen[2];

// ================= helpers =================
__device__ __forceinline__ uint32_t smem_u32(const void* p) {
    uint32_t a;
    asm("{ .reg .u64 t; cvta.to.shared.u64 t, %1; cvt.u32.u64 %0, t; }" : "=r"(a) : "l"(p));
    return a;
}
__device__ __forceinline__ void cp16(uint32_t dst, const void* src) {
    asm volatile("cp.async.cg.shared.global [%0], [%1], 16;" :: "r"(dst), "l"(src) : "memory");
}
__device__ __forceinline__ void ldsm_x4(uint32_t* r, uint32_t addr) {
    asm volatile("ldmatrix.sync.aligned.m8n8.x4.shared.b16 {%0,%1,%2,%3}, [%4];"
                 : "=r"(r[0]), "=r"(r[1]), "=r"(r[2]), "=r"(r[3]) : "r"(addr));
}
__device__ __forceinline__ void mma_f16(float* c, const uint32_t* a, uint32_t b0, uint32_t b1) {
    asm volatile(
        "mma.sync.aligned.m16n8k16.row.col.f32.f16.f16.f32 "
        "{%0,%1,%2,%3}, {%4,%5,%6,%7}, {%8,%9}, {%0,%1,%2,%3};\n"
        : "+f"(c[0]), "+f"(c[1]), "+f"(c[2]), "+f"(c[3])
        : "r"(a[0]), "r"(a[1]), "r"(a[2]), "r"(a[3]), "r"(b0), "r"(b1));
}
__device__ __forceinline__ unsigned ld_acq(unsigned* p) {
    unsigned v;
    asm volatile("ld.acquire.gpu.global.u32 %0, [%1];" : "=r"(v) : "l"(p) : "memory");
    return v;
}

// ================= fp16 mma.sync GEMM (256 threads, 8 warps, 64x32 warp tiles) ====
// CTA tile 128x128. warp_m = wid&1 (64 rows), warp_n = wid>>1 (32 cols).
// mode 0: C = A[M,K]*Bw[4096,K]^T + bias  -> g_xg[dir][m][col]   (dir = n>>11)
// mode 1: same math, N=32000              -> out[B,V,S] scatter
#define RSTR 80                  // bytes per smem row (32 halves + 8 pad)
#define STGB (2 * 128 * RSTR)    // 20480 (A rows 0..127, B rows 128..255)
#define GEMM_DSM 67584           // max(3*STGB=61440, epilogue 128*132*4=67584)

__global__ __launch_bounds__(256, 2) void gemm_mma(
    const __half* __restrict__ A, const __half* __restrict__ Bw,
    const float* __restrict__ bias, float* __restrict__ out,
    int Kdim, int mode)
{
    extern __shared__ char dsmc[];
    float* dsm = reinterpret_cast<float*>(dsmc);
    int tid = threadIdx.x, wid = tid >> 5, lane = tid & 31;
    int warp_m = wid & 1, warp_n = wid >> 1;        // 2 x 4 warps
    int gr = lane >> 2, gc = lane & 3;
    int m0 = blockIdx.x << 7;
    int n0 = blockIdx.y << 7;
    uint32_t base = smem_u32(dsmc);
    int KC = Kdim >> 5;

    const __half* Ag = A + (size_t)m0 * Kdim;
    const __half* Bg = Bw + (size_t)n0 * Kdim;

    // per-thread ldmatrix offsets (bytes)
    uint32_t aoff = (uint32_t)((lane & 15) * RSTR + (lane >> 4) * 16)
                  + (uint32_t)(warp_m * 64 * RSTR);
    uint32_t boff = (uint32_t)(((lane & 7) + ((lane >> 3) & 1) * 8) * RSTR + (lane >> 4) * 16)
                  + (uint32_t)(warp_n * 32 * RSTR) + 128 * RSTR;

    float acc[4][4][4];
#pragma unroll
    for (int mi = 0; mi < 4; mi++)
#pragma unroll
        for (int ni = 0; ni < 4; ni++)
#pragma unroll
            for (int q = 0; q < 4; q++) acc[mi][ni][q] = 0.f;

#define LOAD_STAGE(s, c) do {                                               \
        uint32_t sb_ = base + (s) * STGB;                                   \
        const __half* Ac_ = Ag + (c) * 32;                                  \
        const __half* Bc_ = Bg + (c) * 32;                                  \
        _Pragma("unroll")                                                   \
        for (int q_ = 0; q_ < 4; q_++) {                                    \
            int f_ = q_ * 256 + tid;                                        \
            int row_ = f_ >> 2, g_ = f_ & 3;                                \
            const __half* src_ = (row_ < 128)                               \
                ? Ac_ + (size_t)row_ * Kdim + g_ * 8                        \
                : Bc_ + (size_t)(row_ - 128) * Kdim + g_ * 8;               \
            cp16(sb_ + row_ * RSTR + g_ * 16, src_);                        \
        }                                                                   \
        asm volatile("cp.async.commit_group;" ::: "memory");                \
    } while (0)

    LOAD_STAGE(0, 0);
    LOAD_STAGE(1, 1);
    LOAD_STAGE(2, 2);

    int s = 0;
    for (int c = 0; c < KC; c++) {
        asm volatile("cp.async.wait_group 2;" ::: "memory");
        __syncthreads();
        uint32_t sb = base + s * STGB;
#pragma unroll
        for (int kb = 0; kb < 64; kb += 32) {   // two k16 sub-steps
            uint32_t af[4][4], bf[2][4];
#pragma unroll
            for (int mi = 0; mi < 4; mi++)
                ldsm_x4(af[mi], sb + aoff + (uint32_t)(mi * 16 * RSTR) + kb);
#pragma unroll
            for (int nj = 0; nj < 2; nj++)
                ldsm_x4(bf[nj], sb + boff + (uint32_t)(nj * 16 * RSTR) + kb);
#pragma unroll
            for (int mi = 0; mi < 4; mi++)
#pragma unroll
                for (int ni = 0; ni < 4; ni++)
                    mma_f16(acc[mi][ni], af[mi],
                            bf[ni >> 1][ni & 1], bf[ni >> 1][2 + (ni & 1)]);
        }
        __syncthreads();
        if (c < KC - 3) LOAD_STAGE(s, c + 3);
        else asm volatile("cp.async.commit_group;" ::: "memory");
        s++; if (s == 3) s = 0;
    }
    asm volatile("cp.async.wait_group 0;" ::: "memory");
    __syncthreads();

    if (mode == 1) {
        // ---- transpose epilogue -> out[B,V,S] ----
        float* es = dsm;  // 128 cols x stride 132
#pragma unroll
        for (int mi = 0; mi < 4; mi++) {
            int row = warp_m * 64 + mi * 16 + gr;
#pragma unroll
            for (int ni = 0; ni < 4; ni++) {
                int col = warp_n * 32 + ni * 8 + gc * 2;
                es[col * 132 + row]           = acc[mi][ni][0];
                es[(col + 1) * 132 + row]     = acc[mi][ni][1];
                es[col * 132 + row + 8]       = acc[mi][ni][2];
                es[(col + 1) * 132 + row + 8] = acc[mi][ni][3];
            }
        }
        __syncthreads();
        int bb = blockIdx.x;
        float* ob = out + (size_t)bb * Vv * Ss;
#pragma unroll 4
        for (int i = 0; i < 16; i++) {
            int f4 = i * 256 + tid;
            int rown = f4 >> 5;
            int c4 = f4 & 31;
            float4 v = *reinterpret_cast<const float4*>(es + rown * 132 + c4 * 4);
            float bv = bias[n0 + rown];
            v.x += bv; v.y += bv; v.z += bv; v.w += bv;
            *reinterpret_cast<float4*>(ob + (size_t)(n0 + rown) * Ss + c4 * 4) = v;
        }
    } else {
        // ---- direct [m][col] stores into g_xg[dir] ----
        int dirq = n0 >> 11;
        float* dst = out + (size_t)dirq * ((size_t)MBr * G4);
        int ncol0 = n0 & 2047;
#pragma unroll
        for (int mi = 0; mi < 4; mi++) {
            int row = m0 + warp_m * 64 + mi * 16 + gr;
#pragma unroll
            for (int ni = 0; ni < 4; ni++) {
                int nglob = n0 + warp_n * 32 + ni * 8 + gc * 2;
                int col = ncol0 + warp_n * 32 + ni * 8 + gc * 2;
                float bv0 = bias[nglob], bv1 = bias[nglob + 1];
                float2 v0 = make_float2(acc[mi][ni][0] + bv0, acc[mi][ni][1] + bv1);
                float2 v1 = make_float2(acc[mi][ni][2] + bv0, acc[mi][ni][3] + bv1);
                *reinterpret_cast<float2*>(dst + (size_t)row * G4 + col) = v0;
                *reinterpret_cast<float2*>(dst + (size_t)(row + 8) * G4 + col) = v1;
            }
        }
    }
#undef LOAD_STAGE
}

// ---------------- fp32 -> fp16 conversion (vectorized) ----------------
__global__ void cvt_half_kernel(const float* __restrict__ in, __half* __restrict__ out) {
    int i = blockIdx.x * blockDim.x + threadIdx.x;
    float4 v = reinterpret_cast<const float4*>(in)[i];
    __half2 h0 = __floats2half2_rn(v.x, v.y);
    __half2 h1 = __floats2half2_rn(v.z, v.w);
    reinterpret_cast<__half2*>(out)[2 * i]     = h0;
    reinterpret_cast<__half2*>(out)[2 * i + 1] = h1;
}

// ---------------- combined bias: [f dirs 0..2047 | b dirs 2048..4095] ----------------
__global__ void bias_comb(const float* __restrict__ b1f, const float* __restrict__ b2f,
                          const float* __restrict__ b1b, const float* __restrict__ b2b) {
    int i = blockIdx.x * blockDim.x + threadIdx.x;   // 0..2047
    g_bias[i] = b1f[i] + b2f[i];
    g_bias[2048 + i] = b1b[i] + b2b[i];
}

// ---------------- embedding gather (fp16 out) ----------------
__global__ void embed_kernel(const int* __restrict__ tok, const float* __restrict__ ew) {
    int sb = blockIdx.x;
    int s = sb >> 4, b = sb & 15;
    int t = tok[b * Ss + s];
    float4 v = reinterpret_cast<const float4*>(ew + (size_t)t * Ee)[threadIdx.x];
    __half2* dst = reinterpret_cast<__half2*>(g_x0h + (size_t)sb * Ee);
    dst[2 * threadIdx.x]     = __floats2half2_rn(v.x, v.y);
    dst[2 * threadIdx.x + 1] = __floats2half2_rn(v.z, v.w);
}

// ================= persistent LSTM (one launch per layer) =================
// grid (64, 2): 64 unit-chunks x 2 dirs. 128 threads. All 128 blocks co-resident.
#define LSTM_DSM ((32 * 512 + 16 * 512 + 32 * 16) * 4)   // 100352 B

__global__ __launch_bounds__(128) void lstm_persist(
    const float* __restrict__ Whh_f, const float* __restrict__ Whh_b, int mode)
{
    extern __shared__ float sm[];
    float* ws = sm;                 // [32 rows][512]
    float* hs = sm + 32 * 512;      // [16 b][512]
    float* zr = hs + 16 * 512;      // [32 rows][16 b]
    int dir = blockIdx.y;
    int u0 = blockIdx.x << 3;
    int tid = threadIdx.x;
    int rg = tid >> 4, ks = tid & 15;
    int gb = tid >> 3, gu = tid & 7;
    const float* Whh = dir ? Whh_b : Whh_f;

    {
        float4* d4 = reinterpret_cast<float4*>(ws);
#pragma unroll 4
        for (int i = 0; i < 32; i++) {
            int f4 = i * 128 + tid;
            int lrr = f4 >> 7, c4 = f4 & 127;
            int R = (lrr >> 3) * Hh + u0 + (lrr & 7);
            d4[f4] = *reinterpret_cast<const float4*>(Whh + (size_t)R * Hh + (c4 << 2));
        }
    }

    float creg = 0.f;
    unsigned mygen = 0;
    if (tid == 0) mygen = ld_acq(&g_bar_gen[dir]);

    for (int t = 0; t < Ss; t++) {
        int tidx = dir ? (Ss - 1 - t) : t;

        {
            float4* h4 = reinterpret_cast<float4*>(hs);
            if (t == 0) {
                float4 z = make_float4(0.f, 0.f, 0.f, 0.f);
#pragma unroll
                for (int i = 0; i < 16; i++) h4[i * 128 + tid] = z;
            } else {
                const float4* src = reinterpret_cast<const float4*>(g_h[t & 1][dir]);
#pragma unroll
                for (int i = 0; i < 16; i++) h4[i * 128 + tid] = __ldcv(src + i * 128 + tid);
            }
        }
        __syncthreads();

        float acc[4][16];
#pragma unroll
        for (int r = 0; r < 4; r++)
#pragma unroll
            for (int b = 0; b < 16; b++) acc[r][b] = 0.f;

#pragma unroll 2
        for (int j = 0; j < 8; j++) {
            int k = (j << 6) + (ks << 2);
            const float* wr = ws + ((rg << 2) * 512) + k;
            float4 w0 = *reinterpret_cast<const float4*>(wr);
            float4 w1 = *reinterpret_cast<const float4*>(wr + 512);
            float4 w2 = *reinterpret_cast<const float4*>(wr + 1024);
            float4 w3 = *reinterpret_cast<const float4*>(wr + 1536);
#pragma unroll
            for (int b = 0; b < 16; b++) {
                float4 hv = *reinterpret_cast<const float4*>(hs + (b << 9) + k);
                acc[0][b] += w0.x * hv.x + w0.y * hv.y + w0.z * hv.z + w0.w * hv.w;
                acc[1][b] += w1.x * hv.x + w1.y * hv.y + w1.z * hv.z + w1.w * hv.w;
                acc[2][b] += w2.x * hv.x + w2.y * hv.y + w2.z * hv.z + w2.w * hv.w;
                acc[3][b] += w3.x * hv.x + w3.y * hv.y + w3.z * hv.z + w3.w * hv.w;
            }
        }

#pragma unroll
        for (int off = 8; off >= 1; off >>= 1)
#pragma unroll
            for (int r = 0; r < 4; r++)
#pragma unroll
                for (int b = 0; b < 16; b++)
                    acc[r][b] += __shfl_xor_sync(0xffffffffu, acc[r][b], off);

        if (ks == 0) {
#pragma unroll
            for (int r = 0; r < 4; r++)
#pragma unroll
                for (int b = 0; b < 16; b++)
                    zr[((rg << 2) + r) * 16 + b] = acc[r][b];
        }
        __syncthreads();

        {
            int unit = u0 + gu;
            const float* xgd = g_xg[dir] + (size_t)(tidx * Bb + gb) * G4 + unit;
            float zi = zr[gu * 16 + gb]        + xgd[0];
            float zf = zr[(8 + gu) * 16 + gb]  + xgd[Hh];
            float zg = zr[(16 + gu) * 16 + gb] + xgd[2 * Hh];
            float zo = zr[(24 + gu) * 16 + gb] + xgd[3 * Hh];
            float ig = 1.f / (1.f + expf(-zi));
            float fg = 1.f / (1.f + expf(-zf));
            float gg = tanhf(zg);
            float og = 1.f / (1.f + expf(-zo));
            creg = fg * creg + ig * gg;
            float h = og * tanhf(creg);
            g_h[(t & 1) ^ 1][dir][gb * Hh + unit] = h;
            if (mode == 0)
                g_x1h[(size_t)(tidx * Bb + gb) * 1024 + (dir << 9) + unit] = __float2half_rn(h);
            else
                g_hfinh[(size_t)gb * (Ss * 1024) + tidx * 1024 + (dir << 9) + unit] = __float2half_rn(h);
        }

        __syncthreads();
        if (tid == 0) {
            __threadfence();
            unsigned arrived = atomicAdd(&g_bar_cnt[dir], 1u);
            mygen++;
            if (arrived == 63u) {
                g_bar_cnt[dir] = 0u;
                asm volatile("red.release.gpu.global.add.u32 [%0], 1;"
                             :: "l"(&g_bar_gen[dir]) : "memory");
            } else {
                while (ld_acq(&g_bar_gen[dir]) != mygen) { }
            }
        }
        __syncthreads();
    }
}

// ---------------- launch ----------------
extern "C" void kernel_launch(void* const* d_in, const int* in_sizes, int n_in,
                              void* d_out, int out_size)
{
    const int*   tok  = (const int*)d_in[0];
    const float* ew   = (const float*)d_in[1];
    const float* Wih0f = (const float*)d_in[2],  *Whh0f = (const float*)d_in[3];
    const float* bih0f = (const float*)d_in[4],  *bhh0f = (const float*)d_in[5];
    const float* Wih0b = (const float*)d_in[6],  *Whh0b = (const float*)d_in[7];
    const float* bih0b = (const float*)d_in[8],  *bhh0b = (const float*)d_in[9];
    const float* Wih1f = (const float*)d_in[10], *Whh1f = (const float*)d_in[11];
    const float* bih1f = (const float*)d_in[12], *bhh1f = (const float*)d_in[13];
    const float* Wih1b = (const float*)d_in[14], *Whh1b = (const float*)d_in[15];
    const float* bih1b = (const float*)d_in[16], *bhh1b = (const float*)d_in[17];
    const float* linw = (const float*)d_in[18],  *linb  = (const float*)d_in[19];
    float* out = (float*)d_out;

    __half *px0, *px1, *phf, *pwt, *pwp;
    float *pxg, *pbias;
    cudaGetSymbolAddress((void**)&px0, g_x0h);
    cudaGetSymbolAddress((void**)&px1, g_x1h);
    cudaGetSymbolAddress((void**)&pxg, g_xg);
    cudaGetSymbolAddress((void**)&phf, g_hfinh);
    cudaGetSymbolAddress((void**)&pwt, g_wth);
    cudaGetSymbolAddress((void**)&pwp, g_wph);
    cudaGetSymbolAddress((void**)&pbias, g_bias);

    cudaFuncSetAttribute(gemm_mma, cudaFuncAttributeMaxDynamicSharedMemorySize, GEMM_DSM);
    cudaFuncSetAttribute(lstm_persist, cudaFuncAttributeMaxDynamicSharedMemorySize, LSTM_DSM);

    embed_kernel<<<MBr, 128>>>(tok, ew);
    cvt_half_kernel<<<(Vv * 1024 / 4) / 256, 256>>>(linw, pwt);

    // ---- layer 0 ----
    cvt_half_kernel<<<(2048 * 512 / 4) / 256, 256>>>(Wih0f, pwp);
    cvt_half_kernel<<<(2048 * 512 / 4) / 256, 256>>>(Wih0b, pwp + (size_t)2048 * 512);
    bias_comb<<<8, 256>>>(bih0f, bhh0f, bih0b, bhh0b);
    gemm_mma<<<dim3(16, 32), 256, GEMM_DSM>>>(px0, pwp, pbias, pxg, 512, 0);
    lstm_persist<<<dim3(64, 2), 128, LSTM_DSM>>>(Whh0f, Whh0b, 0);

    // ---- layer 1 ----
    cvt_half_kernel<<<(2048 * 1024 / 4) / 256, 256>>>(Wih1f, pwp);
    cvt_half_kernel<<<(2048 * 1024 / 4) / 256, 256>>>(Wih1b, pwp + (size_t)2048 * 1024);
    bias_comb<<<8, 256>>>(bih1f, bhh1f, bih1b, bhh1b);
    gemm_mma<<<dim3(16, 32), 256, GEMM_DSM>>>(px1, pwp, pbias, pxg, 1024, 0);
    lstm_persist<<<dim3(64, 2), 128, LSTM_DSM>>>(Whh1f, Whh1b, 1);

    // ---- final projection ----
    gemm_mma<<<dim3(16, 250), 256, GEMM_DSM>>>(phf, pwt, linb, out, 1024, 1);
}

// round 9
// speedup vs baseline: 1.4069x; 1.4069x over previous
#include <cuda_runtime.h>
#include <cuda_fp16.h>
#include <math.h>
#include <stdint.h>

#define Vv  32000
#define Ee  512
#define Hh  512
#define Bb  16
#define Ss  128
#define G4  2048   // 4*H
#define MBr 2048   // S*B rows

// ---------------- scratch (static device memory; no allocation) ----------------
__device__ __half g_x0h[(size_t)MBr * Ee];        // layer0 input (fp16)
__device__ __half g_x1h[(size_t)MBr * 1024];      // layer1 input (fp16)
__device__ float  g_xg[2][(size_t)MBr * G4];      // per-dir gate preacts (fp32)
__device__ __half g_hh[2][2][Bb * Hh];            // [parity][dir][b*H] (fp16)
__device__ __half g_hfinh[(size_t)Bb * Ss * 1024];// layer1 output (fp16)
__device__ __half g_wth[(size_t)Vv * 1024];       // lin_w fp16
__device__ __half g_wph[(size_t)4096 * 1024];     // packed Wih fp16 (both dirs)
__device__ float  g_bias[4096];                   // combined bih+bhh (both dirs)
__device__ unsigned g_bar_cnt[2];
__device__ unsigned g_bar_gen[2];

// ================= helpers =================
__device__ __forceinline__ uint32_t smem_u32(const void* p) {
    uint32_t a;
    asm("{ .reg .u64 t; cvta.to.shared.u64 t, %1; cvt.u32.u64 %0, t; }" : "=r"(a) : "l"(p));
    return a;
}
__device__ __forceinline__ void cp16(uint32_t dst, const void* src) {
    asm volatile("cp.async.cg.shared.global [%0], [%1], 16;" :: "r"(dst), "l"(src) : "memory");
}
__device__ __forceinline__ void ldsm_x4(uint32_t* r, uint32_t addr) {
    asm volatile("ldmatrix.sync.aligned.m8n8.x4.shared.b16 {%0,%1,%2,%3}, [%4];"
                 : "=r"(r[0]), "=r"(r[1]), "=r"(r[2]), "=r"(r[3]) : "r"(addr));
}
__device__ __forceinline__ void mma_f16(float* c, const uint32_t* a, uint32_t b0, uint32_t b1) {
    asm volatile(
        "mma.sync.aligned.m16n8k16.row.col.f32.f16.f16.f32 "
        "{%0,%1,%2,%3}, {%4,%5,%6,%7}, {%8,%9}, {%0,%1,%2,%3};\n"
        : "+f"(c[0]), "+f"(c[1]), "+f"(c[2]), "+f"(c[3])
        : "r"(a[0]), "r"(a[1]), "r"(a[2]), "r"(a[3]), "r"(b0), "r"(b1));
}
__device__ __forceinline__ unsigned ld_acq(unsigned* p) {
    unsigned v;
    asm volatile("ld.acquire.gpu.global.u32 %0, [%1];" : "=r"(v) : "l"(p) : "memory");
    return v;
}

// ================= fp16 mma.sync GEMM (R7 config: 128 thr, 64x64 warp tiles) =====
#define RSTR 80                  // bytes per smem row (32 halves + 8 pad)
#define STGB (2 * 128 * RSTR)    // 20480
#define GEMM_DSM 67584           // max(3*STGB=61440, epilogue 128*132*4=67584)

__global__ __launch_bounds__(128) void gemm_mma(
    const __half* __restrict__ A, const __half* __restrict__ Bw,
    const float* __restrict__ bias, float* __restrict__ out,
    int Kdim, int mode)
{
    extern __shared__ char dsmc[];
    float* dsm = reinterpret_cast<float*>(dsmc);
    int tid = threadIdx.x, wid = tid >> 5, lane = tid & 31;
    int warp_m = wid & 1, warp_n = wid >> 1;
    int gr = lane >> 2, gc = lane & 3;
    int m0 = blockIdx.x << 7;
    int n0 = blockIdx.y << 7;
    uint32_t base = smem_u32(dsmc);
    int KC = Kdim >> 5;

    const __half* Ag = A + (size_t)m0 * Kdim;
    const __half* Bg = Bw + (size_t)n0 * Kdim;

    uint32_t aoff = (uint32_t)((lane & 15) * RSTR + (lane >> 4) * 16)
                  + (uint32_t)(warp_m * 64 * RSTR);
    uint32_t boff = (uint32_t)(((lane & 7) + ((lane >> 3) & 1) * 8) * RSTR + (lane >> 4) * 16)
                  + (uint32_t)(warp_n * 64 * RSTR) + 128 * RSTR;

    float acc[4][8][4];
#pragma unroll
    for (int mi = 0; mi < 4; mi++)
#pragma unroll
        for (int ni = 0; ni < 8; ni++)
#pragma unroll
            for (int q = 0; q < 4; q++) acc[mi][ni][q] = 0.f;

#define LOAD_STAGE(s, c) do {                                               \
        uint32_t sb_ = base + (s) * STGB;                                   \
        const __half* Ac_ = Ag + (c) * 32;                                  \
        const __half* Bc_ = Bg + (c) * 32;                                  \
        _Pragma("unroll")                                                   \
        for (int q_ = 0; q_ < 4; q_++) {                                    \
            int f_ = q_ * 128 + tid;                                        \
            int row_ = f_ >> 2, g_ = f_ & 3;                                \
            cp16(sb_ + row_ * RSTR + g_ * 16,                               \
                 Ac_ + (size_t)row_ * Kdim + g_ * 8);                       \
            cp16(sb_ + 128 * RSTR + row_ * RSTR + g_ * 16,                  \
                 Bc_ + (size_t)row_ * Kdim + g_ * 8);                       \
        }                                                                   \
        asm volatile("cp.async.commit_group;" ::: "memory");                \
    } while (0)

    LOAD_STAGE(0, 0);
    LOAD_STAGE(1, 1);
    LOAD_STAGE(2, 2);

    int s = 0;
    for (int c = 0; c < KC; c++) {
        asm volatile("cp.async.wait_group 2;" ::: "memory");
        __syncthreads();
        uint32_t sb = base + s * STGB;
#pragma unroll
        for (int kb = 0; kb < 64; kb += 32) {
            uint32_t af[4][4], bf[4][4];
#pragma unroll
            for (int mi = 0; mi < 4; mi++)
                ldsm_x4(af[mi], sb + aoff + (uint32_t)(mi * 16 * RSTR) + kb);
#pragma unroll
            for (int nj = 0; nj < 4; nj++)
                ldsm_x4(bf[nj], sb + boff + (uint32_t)(nj * 16 * RSTR) + kb);
#pragma unroll
            for (int mi = 0; mi < 4; mi++)
#pragma unroll
                for (int ni = 0; ni < 8; ni++)
                    mma_f16(acc[mi][ni], af[mi],
                            bf[ni >> 1][ni & 1], bf[ni >> 1][2 + (ni & 1)]);
        }
        __syncthreads();
        if (c < KC - 3) LOAD_STAGE(s, c + 3);
        else asm volatile("cp.async.commit_group;" ::: "memory");
        s++; if (s == 3) s = 0;
    }
    asm volatile("cp.async.wait_group 0;" ::: "memory");
    __syncthreads();

    if (mode == 1) {
        float* es = dsm;  // 128 x stride 132
#pragma unroll
        for (int mi = 0; mi < 4; mi++) {
            int row = warp_m * 64 + mi * 16 + gr;
#pragma unroll
            for (int ni = 0; ni < 8; ni++) {
                int col = warp_n * 64 + ni * 8 + gc * 2;
                es[col * 132 + row]           = acc[mi][ni][0];
                es[(col + 1) * 132 + row]     = acc[mi][ni][1];
                es[col * 132 + row + 8]       = acc[mi][ni][2];
                es[(col + 1) * 132 + row + 8] = acc[mi][ni][3];
            }
        }
        __syncthreads();
        int bb = blockIdx.x;
        float* ob = out + (size_t)bb * Vv * Ss;
#pragma unroll 4
        for (int i = 0; i < 32; i++) {
            int f4 = i * 128 + tid;
            int rown = f4 >> 5;
            int c4 = f4 & 31;
            float4 v = *reinterpret_cast<const float4*>(es + rown * 132 + c4 * 4);
            float bv = bias[n0 + rown];
            v.x += bv; v.y += bv; v.z += bv; v.w += bv;
            *reinterpret_cast<float4*>(ob + (size_t)(n0 + rown) * Ss + c4 * 4) = v;
        }
    } else {
        int dirq = n0 >> 11;
        float* dst = out + (size_t)dirq * ((size_t)MBr * G4);
        int ncol0 = n0 & 2047;
#pragma unroll
        for (int mi = 0; mi < 4; mi++) {
            int row = m0 + warp_m * 64 + mi * 16 + gr;
#pragma unroll
            for (int ni = 0; ni < 8; ni++) {
                int nglob = n0 + warp_n * 64 + ni * 8 + gc * 2;
                int col = ncol0 + warp_n * 64 + ni * 8 + gc * 2;
                float bv0 = bias[nglob], bv1 = bias[nglob + 1];
                float2 v0 = make_float2(acc[mi][ni][0] + bv0, acc[mi][ni][1] + bv1);
                float2 v1 = make_float2(acc[mi][ni][2] + bv0, acc[mi][ni][3] + bv1);
                *reinterpret_cast<float2*>(dst + (size_t)row * G4 + col) = v0;
                *reinterpret_cast<float2*>(dst + (size_t)(row + 8) * G4 + col) = v1;
            }
        }
    }
#undef LOAD_STAGE
}

// ---------------- fp32 -> fp16 conversion (vectorized) ----------------
__global__ void cvt_half_kernel(const float* __restrict__ in, __half* __restrict__ out) {
    int i = blockIdx.x * blockDim.x + threadIdx.x;
    float4 v = reinterpret_cast<const float4*>(in)[i];
    reinterpret_cast<__half2*>(out)[2 * i]     = __floats2half2_rn(v.x, v.y);
    reinterpret_cast<__half2*>(out)[2 * i + 1] = __floats2half2_rn(v.z, v.w);
}

// ---------------- combined bias ----------------
__global__ void bias_comb(const float* __restrict__ b1f, const float* __restrict__ b2f,
                          const float* __restrict__ b1b, const float* __restrict__ b2b) {
    int i = blockIdx.x * blockDim.x + threadIdx.x;
    g_bias[i] = b1f[i] + b2f[i];
    g_bias[2048 + i] = b1b[i] + b2b[i];
}

// ---------------- embedding gather (fp16 out) ----------------
__global__ void embed_kernel(const int* __restrict__ tok, const float* __restrict__ ew) {
    int sb = blockIdx.x;
    int s = sb >> 4, b = sb & 15;
    int t = tok[b * Ss + s];
    float4 v = reinterpret_cast<const float4*>(ew + (size_t)t * Ee)[threadIdx.x];
    __half2* dst = reinterpret_cast<__half2*>(g_x0h + (size_t)sb * Ee);
    dst[2 * threadIdx.x]     = __floats2half2_rn(v.x, v.y);
    dst[2 * threadIdx.x + 1] = __floats2half2_rn(v.z, v.w);
}

// ================= persistent LSTM with mma recurrence =================
// grid (64, 2). 128 threads / 4 warps. Warp w owns gate w's 8 rows (units u0..u0+7),
// with Whh fragments resident in registers for all 128 steps.
// smem: Whh16 [32 rows][520 halves] | hs16 [16 b][520 halves] | zr [32][16] f32
#define WS16_B 33280                       // 32*520*2
#define HS16_B 16640                       // 16*520*2
#define ZR_OFF (WS16_B + HS16_B)           // 49920
#define LSTM_DSM (ZR_OFF + 32 * 16 * 4)    // 51968

__global__ __launch_bounds__(128) void lstm_persist(
    const float* __restrict__ Whh_f, const float* __restrict__ Whh_b, int mode)
{
    extern __shared__ char sm[];
    __half* ws16 = reinterpret_cast<__half*>(sm);
    float* zr = reinterpret_cast<float*>(sm + ZR_OFF);
    int dir = blockIdx.y;
    int u0 = blockIdx.x << 3;
    int tid = threadIdx.x;
    int wid = tid >> 5, lane = tid & 31;
    int gr = lane >> 2, gc = lane & 3;
    int gb = tid >> 3, gu = tid & 7;
    const float* Whh = dir ? Whh_b : Whh_f;
    uint32_t ws_b = smem_u32(sm);
    uint32_t hs_b = ws_b + WS16_B;

    // ---- stage Whh chunk (fp32 -> fp16), local row r = gate*8 + ui ----
    for (int f4 = tid; f4 < 32 * 128; f4 += 128) {
        int r = f4 >> 7, c4 = f4 & 127;
        int R = (r >> 3) * Hh + u0 + (r & 7);
        float4 v = *reinterpret_cast<const float4*>(Whh + (size_t)R * Hh + (c4 << 2));
        __half2* d = reinterpret_cast<__half2*>(ws16 + r * 520 + (c4 << 2));
        d[0] = __floats2half2_rn(v.x, v.y);
        d[1] = __floats2half2_rn(v.z, v.w);
    }
    __syncthreads();

    // ---- build Whh B-fragments in registers (K=512 -> 16 ldsm.x4 of k32 each) ----
    uint32_t wreg[16][4];
    {
        uint32_t wrow = ws_b + (uint32_t)((wid * 8 + (lane & 7)) * 1040 + (lane >> 3) * 16);
#pragma unroll
        for (int ks = 0; ks < 16; ks++)
            ldsm_x4(wreg[ks], wrow + (uint32_t)(ks * 64));
    }
    __syncthreads();

    uint32_t a_base = hs_b + (uint32_t)((lane & 15) * 1040 + (lane >> 4) * 16);
    float creg = 0.f;
    unsigned mygen = 0;
    if (tid == 0) mygen = ld_acq(&g_bar_gen[dir]);

    int row = tid >> 3, j = tid & 7;
    for (int t = 0; t < Ss; t++) {
        int tidx = dir ? (Ss - 1 - t) : t;

        // ---- stage h_prev (fp16) into hs16 ----
        {
            uint4* dst4 = reinterpret_cast<uint4*>(sm + WS16_B);
            if (t == 0) {
                uint4 z = make_uint4(0, 0, 0, 0);
#pragma unroll
                for (int jj = 0; jj < 8; jj++) dst4[row * 65 + jj * 8 + j] = z;
            } else {
                const uint4* src4 = reinterpret_cast<const uint4*>(g_hh[t & 1][dir]);
#pragma unroll
                for (int jj = 0; jj < 8; jj++)
                    dst4[row * 65 + jj * 8 + j] = __ldcv(src4 + row * 64 + jj * 8 + j);
            }
        }
        __syncthreads();

        // ---- z = h @ Whh^T for this warp's 8 gate-rows ----
        float acc[4] = {0.f, 0.f, 0.f, 0.f};
#pragma unroll
        for (int ks = 0; ks < 32; ks++) {
            uint32_t af[4];
            ldsm_x4(af, a_base + (uint32_t)(ks * 32));
            mma_f16(acc, af, wreg[ks >> 1][(ks & 1) * 2], wreg[ks >> 1][(ks & 1) * 2 + 1]);
        }
        // c0:(b=gr, ui=2gc) c1:(gr, 2gc+1) c2:(gr+8, 2gc) c3:(gr+8, 2gc+1)
        zr[(wid * 8 + 2 * gc) * 16 + gr]         = acc[0];
        zr[(wid * 8 + 2 * gc + 1) * 16 + gr]     = acc[1];
        zr[(wid * 8 + 2 * gc) * 16 + gr + 8]     = acc[2];
        zr[(wid * 8 + 2 * gc + 1) * 16 + gr + 8] = acc[3];
        __syncthreads();

        // ---- gates: thread <-> (b=gb, unit=u0+gu) ----
        {
            int unit = u0 + gu;
            const float* xgd = g_xg[dir] + (size_t)(tidx * Bb + gb) * G4 + unit;
            float zi = zr[gu * 16 + gb]        + xgd[0];
            float zf = zr[(8 + gu) * 16 + gb]  + xgd[Hh];
            float zg = zr[(16 + gu) * 16 + gb] + xgd[2 * Hh];
            float zo = zr[(24 + gu) * 16 + gb] + xgd[3 * Hh];
            float ig = 1.f / (1.f + expf(-zi));
            float fg = 1.f / (1.f + expf(-zf));
            float gg = tanhf(zg);
            float og = 1.f / (1.f + expf(-zo));
            creg = fg * creg + ig * gg;
            float h = og * tanhf(creg);
            __half hh = __float2half_rn(h);
            g_hh[(t & 1) ^ 1][dir][gb * Hh + unit] = hh;
            if (mode == 0)
                g_x1h[(size_t)(tidx * Bb + gb) * 1024 + (dir << 9) + unit] = hh;
            else
                g_hfinh[(size_t)gb * (Ss * 1024) + tidx * 1024 + (dir << 9) + unit] = hh;
        }

        // ---- per-dir grid barrier (64 blocks) ----
        __syncthreads();
        if (tid == 0) {
            __threadfence();
            unsigned arrived = atomicAdd(&g_bar_cnt[dir], 1u);
            mygen++;
            if (arrived == 63u) {
                g_bar_cnt[dir] = 0u;
                asm volatile("red.release.gpu.global.add.u32 [%0], 1;"
                             :: "l"(&g_bar_gen[dir]) : "memory");
            } else {
                while (ld_acq(&g_bar_gen[dir]) != mygen) { }
            }
        }
        __syncthreads();
    }
}

// ---------------- launch ----------------
extern "C" void kernel_launch(void* const* d_in, const int* in_sizes, int n_in,
                              void* d_out, int out_size)
{
    const int*   tok  = (const int*)d_in[0];
    const float* ew   = (const float*)d_in[1];
    const float* Wih0f = (const float*)d_in[2],  *Whh0f = (const float*)d_in[3];
    const float* bih0f = (const float*)d_in[4],  *bhh0f = (const float*)d_in[5];
    const float* Wih0b = (const float*)d_in[6],  *Whh0b = (const float*)d_in[7];
    const float* bih0b = (const float*)d_in[8],  *bhh0b = (const float*)d_in[9];
    const float* Wih1f = (const float*)d_in[10], *Whh1f = (const float*)d_in[11];
    const float* bih1f = (const float*)d_in[12], *bhh1f = (const float*)d_in[13];
    const float* Wih1b = (const float*)d_in[14], *Whh1b = (const float*)d_in[15];
    const float* bih1b = (const float*)d_in[16], *bhh1b = (const float*)d_in[17];
    const float* linw = (const float*)d_in[18],  *linb  = (const float*)d_in[19];
    float* out = (float*)d_out;

    __half *px0, *px1, *phf, *pwt, *pwp;
    float *pxg, *pbias;
    cudaGetSymbolAddress((void**)&px0, g_x0h);
    cudaGetSymbolAddress((void**)&px1, g_x1h);
    cudaGetSymbolAddress((void**)&pxg, g_xg);
    cudaGetSymbolAddress((void**)&phf, g_hfinh);
    cudaGetSymbolAddress((void**)&pwt, g_wth);
    cudaGetSymbolAddress((void**)&pwp, g_wph);
    cudaGetSymbolAddress((void**)&pbias, g_bias);

    cudaFuncSetAttribute(gemm_mma, cudaFuncAttributeMaxDynamicSharedMemorySize, GEMM_DSM);
    cudaFuncSetAttribute(lstm_persist, cudaFuncAttributeMaxDynamicSharedMemorySize, LSTM_DSM);

    embed_kernel<<<MBr, 128>>>(tok, ew);
    cvt_half_kernel<<<(Vv * 1024 / 4) / 256, 256>>>(linw, pwt);

    // ---- layer 0 ----
    cvt_half_kernel<<<(2048 * 512 / 4) / 256, 256>>>(Wih0f, pwp);
    cvt_half_kernel<<<(2048 * 512 / 4) / 256, 256>>>(Wih0b, pwp + (size_t)2048 * 512);
    bias_comb<<<8, 256>>>(bih0f, bhh0f, bih0b, bhh0b);
    gemm_mma<<<dim3(16, 32), 128, GEMM_DSM>>>(px0, pwp, pbias, pxg, 512, 0);
    lstm_persist<<<dim3(64, 2), 128, LSTM_DSM>>>(Whh0f, Whh0b, 0);

    // ---- layer 1 ----
    cvt_half_kernel<<<(2048 * 1024 / 4) / 256, 256>>>(Wih1f, pwp);
    cvt_half_kernel<<<(2048 * 1024 / 4) / 256, 256>>>(Wih1b, pwp + (size_t)2048 * 1024);
    bias_comb<<<8, 256>>>(bih1f, bhh1f, bih1b, bhh1b);
    gemm_mma<<<dim3(16, 32), 128, GEMM_DSM>>>(px1, pwp, pbias, pxg, 1024, 0);
    lstm_persist<<<dim3(64, 2), 128, LSTM_DSM>>>(Whh1f, Whh1b, 1);

    // ---- final projection ----
    gemm_mma<<<dim3(16, 250), 128, GEMM_DSM>>>(phf, pwt, linb, out, 1024, 1);
}